// round 9
// baseline (speedup 1.0000x reference)
#include <cuda_runtime.h>
#include <cuda_bf16.h>

#define FEAT_C 512
#define FEAT_H 100
#define FEAT_W 152
#define NUM_ROIS 512
#define AH 14
#define AW 14
#define SPATIAL_SCALE 0.0625f
#define CH_CHUNK 16
#define CHUNKS_PER_ROI (FEAT_C / CH_CHUNK)   // 32
#define BINS (AH * AW)                       // 196
#define HW (FEAT_H * FEAT_W)

// Separable RoI-align, v4 = R7 (best, 80.4us) + occupancy fix only:
//  - warp = one ph-pair, lanes = coalesced feature-row span, y-lerp lane-wise,
//    x-interp via dynamic shuffles.
//  - CH_CHUNK 16: body ~5.6KB SASS, fits L0 I$ (32 blew it: R8 regression).
//  - chunk-major order: 512 consecutive blocks share a 1.9MB channel slice.
//  - launch_bounds(224,7): 49 warps (77% occ), reg cap 41; kernel needs 40.
__global__ __launch_bounds__(224, 7) void roi_align_kernel(
    const float* __restrict__ feat,
    const float* __restrict__ rois,
    float* __restrict__ out)
{
    const int r     = blockIdx.x & (NUM_ROIS - 1);      // % 512
    const int chunk = blockIdx.x >> 9;                  // / 512
    const int c0    = chunk * CH_CHUNK;

    const int tid  = threadIdx.x;
    const int wid  = tid >> 5;                          // 0..6 -> ph pair
    const int lane = tid & 31;

    // ---- roi params ----
    const float* rp = rois + r * 5;
    const int   b       = (int)rp[0];
    const float x_start = rp[1] * SPATIAL_SCALE;
    const float y_start = rp[2] * SPATIAL_SCALE;
    const float x_end   = rp[3] * SPATIAL_SCALE;
    const float y_end   = rp[4] * SPATIAL_SCALE;

    const float roi_w = fmaxf(x_end - x_start, 0.0f);
    const float roi_h = fmaxf(y_end - y_start, 0.0f);
    const float bin_h = roi_h * (1.0f / (float)(AH - 1));
    const float bin_w = roi_w * (1.0f / (float)(AW - 1));

    // ---- x footprint (uniform across block): span <= 29 floats ----
    const float xs0c = fminf(fmaxf(x_start, 0.0f), (float)(FEAT_W - 1));
    const float xsEc = fminf(fmaxf(x_end,   0.0f), (float)(FEAT_W - 1));
    const int x_lo = (int)floorf(xs0c);
    const int x_hi = min((int)floorf(xsEc) + 1, FEAT_W - 1);
    const int nx   = x_hi - x_lo + 1;

    // ---- per-lane x interp params ----
    const int pw = (lane < 16) ? min(lane, AW - 1) : min(lane - 16, AW - 1);
    float xs = x_start + (float)pw * bin_w;
    xs = fminf(fmaxf(xs, 0.0f), (float)(FEAT_W - 1));
    const int   x0  = (int)floorf(xs);
    const int   x1  = min(x0 + 1, FEAT_W - 1);
    const float wx  = xs - (float)x0;
    const int   sx0 = x0 - x_lo;
    const int   sx1 = x1 - x_lo;

    // ---- per-warp y params ----
    const int ph_a = wid * 2;
    float ysa = y_start + (float)ph_a * bin_h;
    float ysb = y_start + (float)(ph_a + 1) * bin_h;
    ysa = fminf(fmaxf(ysa, 0.0f), (float)(FEAT_H - 1));
    ysb = fminf(fmaxf(ysb, 0.0f), (float)(FEAT_H - 1));
    const int   ya0 = (int)floorf(ysa);
    const int   ya1 = min(ya0 + 1, FEAT_H - 1);
    const float wya = ysa - (float)ya0;
    const int   yb0 = (int)floorf(ysb);
    const int   yb1 = min(yb0 + 1, FEAT_H - 1);
    const float wyb = ysb - (float)yb0;
    const bool  reuse = (yb0 == ya1);

    const bool ldok = (lane < nx);
    const float* base = feat + ((size_t)b * FEAT_C + c0) * HW + x_lo;
    const int oa0 = ya0 * FEAT_W, oa1 = ya1 * FEAT_W;
    const int ob0 = yb0 * FEAT_W, ob1 = yb1 * FEAT_W;

    float* op = out + ((size_t)r * FEAT_C + c0) * BINS + ph_a * AW;
    const bool stok = (lane < 14) || (lane >= 16 && lane < 30);
    const int  soff = (lane < 14) ? lane : (lane - 2);

    #pragma unroll
    for (int cc = 0; cc < CH_CHUNK; cc++) {
        const float* f = base + cc * HW;
        float ra0 = ldok ? __ldg(f + oa0 + lane) : 0.0f;
        float ra1 = ldok ? __ldg(f + oa1 + lane) : 0.0f;
        float rb1 = ldok ? __ldg(f + ob1 + lane) : 0.0f;
        float rb0;
        if (reuse) {
            rb0 = ra1;
        } else {
            rb0 = ldok ? __ldg(f + ob0 + lane) : 0.0f;
        }

        const float la = fmaf(wya, ra1 - ra0, ra0);
        const float lb = fmaf(wyb, rb1 - rb0, rb0);

        const float a0 = __shfl_sync(0xffffffffu, la, sx0);
        const float a1 = __shfl_sync(0xffffffffu, la, sx1);
        const float b0 = __shfl_sync(0xffffffffu, lb, sx0);
        const float b1 = __shfl_sync(0xffffffffu, lb, sx1);

        const float s0 = (lane < 16) ? a0 : b0;
        const float s1 = (lane < 16) ? a1 : b1;
        const float v  = fmaf(wx, s1 - s0, s0);

        if (stok) op[cc * BINS + soff] = v;
    }
}

extern "C" void kernel_launch(void* const* d_in, const int* in_sizes, int n_in,
                              void* d_out, int out_size)
{
    const float* feat = (const float*)d_in[0];
    const float* rois = (const float*)d_in[1];
    float* out = (float*)d_out;

    dim3 grid(NUM_ROIS * CHUNKS_PER_ROI);   // 16384, chunk-major
    dim3 block(224);
    roi_align_kernel<<<grid, block>>>(feat, rois, out);
}

// round 10
// speedup vs baseline: 1.0738x; 1.0738x over previous
#include <cuda_runtime.h>
#include <cuda_bf16.h>

#define FEAT_C 512
#define FEAT_H 100
#define FEAT_W 152
#define NUM_ROIS 512
#define AH 14
#define AW 14
#define SPATIAL_SCALE 0.0625f
#define CH_CHUNK 16
#define CHUNKS_PER_ROI (FEAT_C / CH_CHUNK)   // 32
#define BINS (AH * AW)                       // 196
#define HW (FEAT_H * FEAT_W)

// Separable RoI-align, v5 = R7 structure (best: 80.4us) + 2-channel
// interleaved load batches for MLP ~8:
//  - warp = one ph-pair, lanes = coalesced feature-row span, y-lerp lane-wise,
//    x-interp via dynamic shuffles.
//  - chunk-major order: 512 consecutive blocks share a 1.9MB channel slice.
//  - launch_bounds(224,6): the ONLY config where ptxas keeps 40-48 regs
//    (minblocks=7 or CH_CHUNK=32 both collapse to 32 regs + spill: R8/R9).
//  - inner loop: 2 channels/iter, 6-8 independent named-scalar loads issued
//    up-front (no arrays -> no spill; no rotation -> no serial chain).
__global__ __launch_bounds__(224, 6) void roi_align_kernel(
    const float* __restrict__ feat,
    const float* __restrict__ rois,
    float* __restrict__ out)
{
    const int r     = blockIdx.x & (NUM_ROIS - 1);      // % 512
    const int chunk = blockIdx.x >> 9;                  // / 512
    const int c0    = chunk * CH_CHUNK;

    const int tid  = threadIdx.x;
    const int wid  = tid >> 5;                          // 0..6 -> ph pair
    const int lane = tid & 31;

    // ---- roi params ----
    const float* rp = rois + r * 5;
    const int   b       = (int)rp[0];
    const float x_start = rp[1] * SPATIAL_SCALE;
    const float y_start = rp[2] * SPATIAL_SCALE;
    const float x_end   = rp[3] * SPATIAL_SCALE;
    const float y_end   = rp[4] * SPATIAL_SCALE;

    const float roi_w = fmaxf(x_end - x_start, 0.0f);
    const float roi_h = fmaxf(y_end - y_start, 0.0f);
    const float bin_h = roi_h * (1.0f / (float)(AH - 1));
    const float bin_w = roi_w * (1.0f / (float)(AW - 1));

    // ---- x footprint (uniform across block): span <= 29 floats ----
    const float xs0c = fminf(fmaxf(x_start, 0.0f), (float)(FEAT_W - 1));
    const float xsEc = fminf(fmaxf(x_end,   0.0f), (float)(FEAT_W - 1));
    const int x_lo = (int)floorf(xs0c);
    const int x_hi = min((int)floorf(xsEc) + 1, FEAT_W - 1);
    const int nx   = x_hi - x_lo + 1;

    // ---- per-lane x interp params ----
    const int pw = (lane < 16) ? min(lane, AW - 1) : min(lane - 16, AW - 1);
    float xs = x_start + (float)pw * bin_w;
    xs = fminf(fmaxf(xs, 0.0f), (float)(FEAT_W - 1));
    const int   x0  = (int)floorf(xs);
    const int   x1  = min(x0 + 1, FEAT_W - 1);
    const float wx  = xs - (float)x0;
    const int   sx0 = x0 - x_lo;
    const int   sx1 = x1 - x_lo;

    // ---- per-warp y params ----
    const int ph_a = wid * 2;
    float ysa = y_start + (float)ph_a * bin_h;
    float ysb = y_start + (float)(ph_a + 1) * bin_h;
    ysa = fminf(fmaxf(ysa, 0.0f), (float)(FEAT_H - 1));
    ysb = fminf(fmaxf(ysb, 0.0f), (float)(FEAT_H - 1));
    const int   ya0 = (int)floorf(ysa);
    const int   ya1 = min(ya0 + 1, FEAT_H - 1);
    const float wya = ysa - (float)ya0;
    const int   yb0 = (int)floorf(ysb);
    const int   yb1 = min(yb0 + 1, FEAT_H - 1);
    const float wyb = ysb - (float)yb0;
    const bool  reuse = (yb0 == ya1);

    const bool ldok = (lane < nx);
    const float* base = feat + ((size_t)b * FEAT_C + c0) * HW + x_lo;
    const int oa0 = ya0 * FEAT_W, oa1 = ya1 * FEAT_W;
    const int ob0 = yb0 * FEAT_W, ob1 = yb1 * FEAT_W;

    float* op = out + ((size_t)r * FEAT_C + c0) * BINS + ph_a * AW;
    const bool stok = (lane < 14) || (lane >= 16 && lane < 30);
    const int  soff = (lane < 14) ? lane : (lane - 2);

    #pragma unroll
    for (int cc = 0; cc < CH_CHUNK; cc += 2) {
        const float* fA = base + cc * HW;
        const float* fB = fA + HW;

        // -------- load batch: 6-8 independent named-scalar LDGs --------
        float Ara0 = ldok ? __ldg(fA + oa0 + lane) : 0.0f;
        float Ara1 = ldok ? __ldg(fA + oa1 + lane) : 0.0f;
        float Arb1 = ldok ? __ldg(fA + ob1 + lane) : 0.0f;
        float Bra0 = ldok ? __ldg(fB + oa0 + lane) : 0.0f;
        float Bra1 = ldok ? __ldg(fB + oa1 + lane) : 0.0f;
        float Brb1 = ldok ? __ldg(fB + ob1 + lane) : 0.0f;
        float Arb0, Brb0;
        if (reuse) {
            Arb0 = Ara1;
            Brb0 = Bra1;
        } else {
            Arb0 = ldok ? __ldg(fA + ob0 + lane) : 0.0f;
            Brb0 = ldok ? __ldg(fB + ob0 + lane) : 0.0f;
        }

        // -------- channel A --------
        const float Ala = fmaf(wya, Ara1 - Ara0, Ara0);
        const float Alb = fmaf(wyb, Arb1 - Arb0, Arb0);
        const float Aa0 = __shfl_sync(0xffffffffu, Ala, sx0);
        const float Aa1 = __shfl_sync(0xffffffffu, Ala, sx1);
        const float Ab0 = __shfl_sync(0xffffffffu, Alb, sx0);
        const float Ab1 = __shfl_sync(0xffffffffu, Alb, sx1);
        const float As0 = (lane < 16) ? Aa0 : Ab0;
        const float As1 = (lane < 16) ? Aa1 : Ab1;
        const float Av  = fmaf(wx, As1 - As0, As0);

        // -------- channel B --------
        const float Bla = fmaf(wya, Bra1 - Bra0, Bra0);
        const float Blb = fmaf(wyb, Brb1 - Brb0, Brb0);
        const float Ba0 = __shfl_sync(0xffffffffu, Bla, sx0);
        const float Ba1 = __shfl_sync(0xffffffffu, Bla, sx1);
        const float Bb0 = __shfl_sync(0xffffffffu, Blb, sx0);
        const float Bb1 = __shfl_sync(0xffffffffu, Blb, sx1);
        const float Bs0 = (lane < 16) ? Ba0 : Bb0;
        const float Bs1 = (lane < 16) ? Ba1 : Bb1;
        const float Bv  = fmaf(wx, Bs1 - Bs0, Bs0);

        if (stok) {
            op[cc * BINS + soff]       = Av;
            op[(cc + 1) * BINS + soff] = Bv;
        }
    }
}

extern "C" void kernel_launch(void* const* d_in, const int* in_sizes, int n_in,
                              void* d_out, int out_size)
{
    const float* feat = (const float*)d_in[0];
    const float* rois = (const float*)d_in[1];
    float* out = (float*)d_out;

    dim3 grid(NUM_ROIS * CHUNKS_PER_ROI);   // 16384, chunk-major
    dim3 block(224);
    roi_align_kernel<<<grid, block>>>(feat, rois, out);
}

// round 11
// speedup vs baseline: 1.3417x; 1.2495x over previous
#include <cuda_runtime.h>
#include <cuda_bf16.h>

#define FEAT_C 512
#define FEAT_H 100
#define FEAT_W 152
#define NUM_ROIS 512
#define AH 14
#define AW 14
#define SPATIAL_SCALE 0.0625f
#define CH_CHUNK 16
#define CHUNKS_PER_ROI (FEAT_C / CH_CHUNK)   // 32
#define BINS (AH * AW)                       // 196
#define HW (FEAT_H * FEAT_W)

// Separable RoI-align, v6 = R7 (best: 80.4us) with a leaner inner body:
//  - warp = one ph-pair, lanes = coalesced feature-row span, y-lerp lane-wise,
//    x-interp via dynamic shuffles.  CH_CHUNK=16, chunk-major, (224,6): the
//    proven config (minblocks=7 / CH=32 / batch-8 all regressed: R8/R9/R10).
//  - branchless body: row-reuse resolved in setup (orb0 = reuse ? oa1 : ob0),
//    removing 16 unrolled uniform branches + duplicated arms.
//  - guardless loads: lane_off = min(lane, nx-1) in setup; out-of-span lanes
//    duplicate the last valid element (same line; never consumed by shuffles
//    or stores since sx0,sx1 <= nx-1).
__global__ __launch_bounds__(224, 6) void roi_align_kernel(
    const float* __restrict__ feat,
    const float* __restrict__ rois,
    float* __restrict__ out)
{
    const int r     = blockIdx.x & (NUM_ROIS - 1);      // % 512
    const int chunk = blockIdx.x >> 9;                  // / 512
    const int c0    = chunk * CH_CHUNK;

    const int tid  = threadIdx.x;
    const int wid  = tid >> 5;                          // 0..6 -> ph pair
    const int lane = tid & 31;

    // ---- roi params ----
    const float* rp = rois + r * 5;
    const int   b       = (int)rp[0];
    const float x_start = rp[1] * SPATIAL_SCALE;
    const float y_start = rp[2] * SPATIAL_SCALE;
    const float x_end   = rp[3] * SPATIAL_SCALE;
    const float y_end   = rp[4] * SPATIAL_SCALE;

    const float roi_w = fmaxf(x_end - x_start, 0.0f);
    const float roi_h = fmaxf(y_end - y_start, 0.0f);
    const float bin_h = roi_h * (1.0f / (float)(AH - 1));
    const float bin_w = roi_w * (1.0f / (float)(AW - 1));

    // ---- x footprint (uniform across block): span <= 29 floats ----
    const float xs0c = fminf(fmaxf(x_start, 0.0f), (float)(FEAT_W - 1));
    const float xsEc = fminf(fmaxf(x_end,   0.0f), (float)(FEAT_W - 1));
    const int x_lo = (int)floorf(xs0c);
    const int x_hi = min((int)floorf(xsEc) + 1, FEAT_W - 1);
    const int nx   = x_hi - x_lo + 1;

    // guardless load offset: lanes >= nx re-load the last valid column
    const int lane_off = min(lane, nx - 1);

    // ---- per-lane x interp params ----
    const int pw = (lane < 16) ? min(lane, AW - 1) : min(lane - 16, AW - 1);
    float xs = x_start + (float)pw * bin_w;
    xs = fminf(fmaxf(xs, 0.0f), (float)(FEAT_W - 1));
    const int   x0  = (int)floorf(xs);
    const int   x1  = min(x0 + 1, FEAT_W - 1);
    const float wx  = xs - (float)x0;
    const int   sx0 = x0 - x_lo;                        // in [0, nx-1]
    const int   sx1 = x1 - x_lo;                        // in [0, nx-1]

    // ---- per-warp y params ----
    const int ph_a = wid * 2;
    float ysa = y_start + (float)ph_a * bin_h;
    float ysb = y_start + (float)(ph_a + 1) * bin_h;
    ysa = fminf(fmaxf(ysa, 0.0f), (float)(FEAT_H - 1));
    ysb = fminf(fmaxf(ysb, 0.0f), (float)(FEAT_H - 1));
    const int   ya0 = (int)floorf(ysa);
    const int   ya1 = min(ya0 + 1, FEAT_H - 1);
    const float wya = ysa - (float)ya0;
    const int   yb0 = (int)floorf(ysb);
    const int   yb1 = min(yb0 + 1, FEAT_H - 1);
    const float wyb = ysb - (float)yb0;

    const float* base = feat + ((size_t)b * FEAT_C + c0) * HW + x_lo + lane_off;
    const int oa0 = ya0 * FEAT_W;
    const int oa1 = ya1 * FEAT_W;
    const int ob1 = yb1 * FEAT_W;
    // branchless row reuse: when yb0 == ya1 this aliases oa1 (same line, L1 hit)
    const int ob0 = yb0 * FEAT_W;

    float* op = out + ((size_t)r * FEAT_C + c0) * BINS + ph_a * AW;
    const bool stok = (lane < 14) || (lane >= 16 && lane < 30);
    const int  soff = (lane < 14) ? lane : (lane - 2);

    #pragma unroll
    for (int cc = 0; cc < CH_CHUNK; cc++) {
        const float* f = base + cc * HW;
        // 4 unconditional coalesced row-span loads
        const float ra0 = __ldg(f + oa0);
        const float ra1 = __ldg(f + oa1);
        const float rb0 = __ldg(f + ob0);
        const float rb1 = __ldg(f + ob1);

        // y-lerp lane-wise
        const float la = fmaf(wya, ra1 - ra0, ra0);
        const float lb = fmaf(wyb, rb1 - rb0, rb0);

        // x-interp via dynamic shuffles
        const float a0 = __shfl_sync(0xffffffffu, la, sx0);
        const float a1 = __shfl_sync(0xffffffffu, la, sx1);
        const float b0 = __shfl_sync(0xffffffffu, lb, sx0);
        const float b1 = __shfl_sync(0xffffffffu, lb, sx1);

        const float s0 = (lane < 16) ? a0 : b0;
        const float s1 = (lane < 16) ? a1 : b1;
        const float v  = fmaf(wx, s1 - s0, s0);

        if (stok) op[cc * BINS + soff] = v;
    }
}

extern "C" void kernel_launch(void* const* d_in, const int* in_sizes, int n_in,
                              void* d_out, int out_size)
{
    const float* feat = (const float*)d_in[0];
    const float* rois = (const float*)d_in[1];
    float* out = (float*)d_out;

    dim3 grid(NUM_ROIS * CHUNKS_PER_ROI);   // 16384, chunk-major
    dim3 block(224);
    roi_align_kernel<<<grid, block>>>(feat, rois, out);
}

// round 12
// speedup vs baseline: 1.6117x; 1.2012x over previous
#include <cuda_runtime.h>
#include <cuda_bf16.h>

#define FEAT_C 512
#define FEAT_H 100
#define FEAT_W 152
#define NUM_ROIS 512
#define AH 14
#define AW 14
#define SPATIAL_SCALE 0.0625f
#define CH_CHUNK 16
#define CHUNKS_PER_ROI (FEAT_C / CH_CHUNK)   // 32
#define BINS (AH * AW)                       // 196
#define HW (FEAT_H * FEAT_W)

// Separable RoI-align, v7 = R7 (best: 80.4us) + two-shuffle fast path.
//  - warp = one ph-pair; chunk-major; CH_CHUNK=16; launch_bounds(224,6)
//    (the only stable reg config: 40-48 regs, no spill).
//  - FAST PATH (nx<=16, ~48% of rois, block-uniform): la in lanes 0-15,
//    lb in lanes 16-31 -> each half-warp sources from its own half:
//    2 LDG + 2 dynamic SHFL + 1 STG per channel (vs 3.5 LDG + 4 SHFL + 1 STG).
//  - SLOW PATH (nx>16): R7 body verbatim (span in all lanes, 4 shuffles,
//    reuse branch kept - it paid for itself, R11 proved).
__global__ __launch_bounds__(224, 6) void roi_align_kernel(
    const float* __restrict__ feat,
    const float* __restrict__ rois,
    float* __restrict__ out)
{
    const int r     = blockIdx.x & (NUM_ROIS - 1);      // % 512
    const int chunk = blockIdx.x >> 9;                  // / 512
    const int c0    = chunk * CH_CHUNK;

    const int tid  = threadIdx.x;
    const int wid  = tid >> 5;                          // 0..6 -> ph pair
    const int lane = tid & 31;

    // ---- roi params ----
    const float* rp = rois + r * 5;
    const int   b       = (int)rp[0];
    const float x_start = rp[1] * SPATIAL_SCALE;
    const float y_start = rp[2] * SPATIAL_SCALE;
    const float x_end   = rp[3] * SPATIAL_SCALE;
    const float y_end   = rp[4] * SPATIAL_SCALE;

    const float roi_w = fmaxf(x_end - x_start, 0.0f);
    const float roi_h = fmaxf(y_end - y_start, 0.0f);
    const float bin_h = roi_h * (1.0f / (float)(AH - 1));
    const float bin_w = roi_w * (1.0f / (float)(AW - 1));

    // ---- x footprint (uniform across block): span <= 29 floats ----
    const float xs0c = fminf(fmaxf(x_start, 0.0f), (float)(FEAT_W - 1));
    const float xsEc = fminf(fmaxf(x_end,   0.0f), (float)(FEAT_W - 1));
    const int x_lo = (int)floorf(xs0c);
    const int x_hi = min((int)floorf(xsEc) + 1, FEAT_W - 1);
    const int nx   = x_hi - x_lo + 1;

    // ---- per-lane x interp params ----
    const int pw = (lane < 16) ? min(lane, AW - 1) : min(lane - 16, AW - 1);
    float xs = x_start + (float)pw * bin_w;
    xs = fminf(fmaxf(xs, 0.0f), (float)(FEAT_W - 1));
    const int   x0  = (int)floorf(xs);
    const int   x1  = min(x0 + 1, FEAT_W - 1);
    const float wx  = xs - (float)x0;
    const int   sx0 = x0 - x_lo;                        // in [0, nx-1]
    const int   sx1 = x1 - x_lo;                        // in [0, nx-1]

    // ---- per-warp y params ----
    const int ph_a = wid * 2;
    float ysa = y_start + (float)ph_a * bin_h;
    float ysb = y_start + (float)(ph_a + 1) * bin_h;
    ysa = fminf(fmaxf(ysa, 0.0f), (float)(FEAT_H - 1));
    ysb = fminf(fmaxf(ysb, 0.0f), (float)(FEAT_H - 1));
    const int   ya0 = (int)floorf(ysa);
    const int   ya1 = min(ya0 + 1, FEAT_H - 1);
    const float wya = ysa - (float)ya0;
    const int   yb0 = (int)floorf(ysb);
    const int   yb1 = min(yb0 + 1, FEAT_H - 1);
    const float wyb = ysb - (float)yb0;
    const bool  reuse = (yb0 == ya1);

    const float* fbase = feat + ((size_t)b * FEAT_C + c0) * HW + x_lo;
    const int oa0 = ya0 * FEAT_W, oa1 = ya1 * FEAT_W;
    const int ob0 = yb0 * FEAT_W, ob1 = yb1 * FEAT_W;

    float* op = out + ((size_t)r * FEAT_C + c0) * BINS + ph_a * AW;
    const bool stok = (lane < 14) || (lane >= 16 && lane < 30);
    const int  soff = (lane < 14) ? lane : (lane - 2);

    if (nx <= 16) {
        // ================= FAST PATH: 2 loads + 2 shuffles =================
        // lanes 0-15: la for column (lane), lanes 16-31: lb for column (lane-16)
        const int  col     = lane & 15;
        const int  col_off = min(col, nx - 1);
        const bool hi      = (lane >= 16);
        const int  ro0     = hi ? ob0 : oa0;
        const int  ro1     = hi ? ob1 : oa1;
        const float wyl    = hi ? wyb : wya;
        const float* base  = fbase + col_off;
        const int  src0    = (lane & 16) | sx0;         // own half-warp
        const int  src1    = (lane & 16) | sx1;

        #pragma unroll
        for (int cc = 0; cc < CH_CHUNK; cc++) {
            const float* f = base + cc * HW;
            const float r0 = __ldg(f + ro0);
            const float r1 = __ldg(f + ro1);
            const float m  = fmaf(wyl, r1 - r0, r0);    // la in lo half, lb in hi half

            const float s0 = __shfl_sync(0xffffffffu, m, src0);
            const float s1 = __shfl_sync(0xffffffffu, m, src1);
            const float v  = fmaf(wx, s1 - s0, s0);

            if (stok) op[cc * BINS + soff] = v;
        }
    } else {
        // ================= SLOW PATH: R7 body (span in all lanes) ==========
        const bool ldok = (lane < nx);
        const float* base = fbase;

        #pragma unroll
        for (int cc = 0; cc < CH_CHUNK; cc++) {
            const float* f = base + cc * HW;
            float ra0 = ldok ? __ldg(f + oa0 + lane) : 0.0f;
            float ra1 = ldok ? __ldg(f + oa1 + lane) : 0.0f;
            float rb1 = ldok ? __ldg(f + ob1 + lane) : 0.0f;
            float rb0;
            if (reuse) {
                rb0 = ra1;
            } else {
                rb0 = ldok ? __ldg(f + ob0 + lane) : 0.0f;
            }

            const float la = fmaf(wya, ra1 - ra0, ra0);
            const float lb = fmaf(wyb, rb1 - rb0, rb0);

            const float a0 = __shfl_sync(0xffffffffu, la, sx0);
            const float a1 = __shfl_sync(0xffffffffu, la, sx1);
            const float b0 = __shfl_sync(0xffffffffu, lb, sx0);
            const float b1 = __shfl_sync(0xffffffffu, lb, sx1);

            const float s0 = (lane < 16) ? a0 : b0;
            const float s1 = (lane < 16) ? a1 : b1;
            const float v  = fmaf(wx, s1 - s0, s0);

            if (stok) op[cc * BINS + soff] = v;
        }
    }
}

extern "C" void kernel_launch(void* const* d_in, const int* in_sizes, int n_in,
                              void* d_out, int out_size)
{
    const float* feat = (const float*)d_in[0];
    const float* rois = (const float*)d_in[1];
    float* out = (float*)d_out;

    dim3 grid(NUM_ROIS * CHUNKS_PER_ROI);   // 16384, chunk-major
    dim3 block(224);
    roi_align_kernel<<<grid, block>>>(feat, rois, out);
}

// round 14
// speedup vs baseline: 1.6297x; 1.0112x over previous
#include <cuda_runtime.h>
#include <cuda_bf16.h>

#define FEAT_C 512
#define FEAT_H 100
#define FEAT_W 152
#define NUM_ROIS 512
#define AH 14
#define AW 14
#define SPATIAL_SCALE 0.0625f
#define CH_CHUNK 16
#define CHUNKS_PER_ROI (FEAT_C / CH_CHUNK)   // 32
#define BINS (AH * AW)                       // 196
#define HW (FEAT_H * FEAT_W)

// Separable RoI-align, v8 = v7 (71.0us) + fast-path 2-channel interleave.
//  - warp = one ph-pair; chunk-major; CH_CHUNK=16; launch_bounds(224,6)
//    (only stable reg config; minblocks>=7 collapses to 32 regs: R9).
//  - FAST PATH (nx<=16, ~48% of rois): la lanes 0-15 / lb lanes 16-31,
//    one shuffle per bilinear source. NOW 2 channels/iter: 4 independent
//    LDGs up-front (MLP=4, the R7-proven depth; 8 overflowed queue: R10).
//  - SLOW PATH (nx>16): R7 body verbatim (4 shuffles, reuse branch kept).
__global__ __launch_bounds__(224, 6) void roi_align_kernel(
    const float* __restrict__ feat,
    const float* __restrict__ rois,
    float* __restrict__ out)
{
    const int r     = blockIdx.x & (NUM_ROIS - 1);      // % 512
    const int chunk = blockIdx.x >> 9;                  // / 512
    const int c0    = chunk * CH_CHUNK;

    const int tid  = threadIdx.x;
    const int wid  = tid >> 5;                          // 0..6 -> ph pair
    const int lane = tid & 31;

    // ---- roi params ----
    const float* rp = rois + r * 5;
    const int   b       = (int)rp[0];
    const float x_start = rp[1] * SPATIAL_SCALE;
    const float y_start = rp[2] * SPATIAL_SCALE;
    const float x_end   = rp[3] * SPATIAL_SCALE;
    const float y_end   = rp[4] * SPATIAL_SCALE;

    const float roi_w = fmaxf(x_end - x_start, 0.0f);
    const float roi_h = fmaxf(y_end - y_start, 0.0f);
    const float bin_h = roi_h * (1.0f / (float)(AH - 1));
    const float bin_w = roi_w * (1.0f / (float)(AW - 1));

    // ---- x footprint (uniform across block): span <= 29 floats ----
    const float xs0c = fminf(fmaxf(x_start, 0.0f), (float)(FEAT_W - 1));
    const float xsEc = fminf(fmaxf(x_end,   0.0f), (float)(FEAT_W - 1));
    const int x_lo = (int)floorf(xs0c);
    const int x_hi = min((int)floorf(xsEc) + 1, FEAT_W - 1);
    const int nx   = x_hi - x_lo + 1;

    // ---- per-lane x interp params ----
    const int pw = (lane < 16) ? min(lane, AW - 1) : min(lane - 16, AW - 1);
    float xs = x_start + (float)pw * bin_w;
    xs = fminf(fmaxf(xs, 0.0f), (float)(FEAT_W - 1));
    const int   x0  = (int)floorf(xs);
    const int   x1  = min(x0 + 1, FEAT_W - 1);
    const float wx  = xs - (float)x0;
    const int   sx0 = x0 - x_lo;                        // in [0, nx-1]
    const int   sx1 = x1 - x_lo;                        // in [0, nx-1]

    // ---- per-warp y params ----
    const int ph_a = wid * 2;
    float ysa = y_start + (float)ph_a * bin_h;
    float ysb = y_start + (float)(ph_a + 1) * bin_h;
    ysa = fminf(fmaxf(ysa, 0.0f), (float)(FEAT_H - 1));
    ysb = fminf(fmaxf(ysb, 0.0f), (float)(FEAT_H - 1));
    const int   ya0 = (int)floorf(ysa);
    const int   ya1 = min(ya0 + 1, FEAT_H - 1);
    const float wya = ysa - (float)ya0;
    const int   yb0 = (int)floorf(ysb);
    const int   yb1 = min(yb0 + 1, FEAT_H - 1);
    const float wyb = ysb - (float)yb0;
    const bool  reuse = (yb0 == ya1);

    const float* fbase = feat + ((size_t)b * FEAT_C + c0) * HW + x_lo;
    const int oa0 = ya0 * FEAT_W, oa1 = ya1 * FEAT_W;
    const int ob0 = yb0 * FEAT_W, ob1 = yb1 * FEAT_W;

    float* op = out + ((size_t)r * FEAT_C + c0) * BINS + ph_a * AW;
    const bool stok = (lane < 14) || (lane >= 16 && lane < 30);
    const int  soff = (lane < 14) ? lane : (lane - 2);

    if (nx <= 16) {
        // ======== FAST PATH: 2 channels/iter, 4 LDG + 4 SHFL + 2 STG =======
        const int  col     = lane & 15;
        const int  col_off = min(col, nx - 1);
        const bool hi      = (lane >= 16);
        const int  ro0     = hi ? ob0 : oa0;
        const int  ro1     = hi ? ob1 : oa1;
        const float wyl    = hi ? wyb : wya;
        const float* base  = fbase + col_off;
        const int  src0    = (lane & 16) | sx0;         // own half-warp
        const int  src1    = (lane & 16) | sx1;

        #pragma unroll
        for (int cc = 0; cc < CH_CHUNK; cc += 2) {
            const float* fA = base + cc * HW;
            const float* fB = fA + HW;

            // 4 independent loads up-front (MLP=4)
            const float Ar0 = __ldg(fA + ro0);
            const float Ar1 = __ldg(fA + ro1);
            const float Br0 = __ldg(fB + ro0);
            const float Br1 = __ldg(fB + ro1);

            const float Am = fmaf(wyl, Ar1 - Ar0, Ar0);
            const float Bm = fmaf(wyl, Br1 - Br0, Br0);

            const float As0 = __shfl_sync(0xffffffffu, Am, src0);
            const float As1 = __shfl_sync(0xffffffffu, Am, src1);
            const float Bs0 = __shfl_sync(0xffffffffu, Bm, src0);
            const float Bs1 = __shfl_sync(0xffffffffu, Bm, src1);

            const float Av = fmaf(wx, As1 - As0, As0);
            const float Bv = fmaf(wx, Bs1 - Bs0, Bs0);

            if (stok) {
                op[cc * BINS + soff]       = Av;
                op[(cc + 1) * BINS + soff] = Bv;
            }
        }
    } else {
        // ================= SLOW PATH: R7 body (span in all lanes) ==========
        const bool ldok = (lane < nx);
        const float* base = fbase;

        #pragma unroll
        for (int cc = 0; cc < CH_CHUNK; cc++) {
            const float* f = base + cc * HW;
            float ra0 = ldok ? __ldg(f + oa0 + lane) : 0.0f;
            float ra1 = ldok ? __ldg(f + oa1 + lane) : 0.0f;
            float rb1 = ldok ? __ldg(f + ob1 + lane) : 0.0f;
            float rb0;
            if (reuse) {
                rb0 = ra1;
            } else {
                rb0 = ldok ? __ldg(f + ob0 + lane) : 0.0f;
            }

            const float la = fmaf(wya, ra1 - ra0, ra0);
            const float lb = fmaf(wyb, rb1 - rb0, rb0);

            const float a0 = __shfl_sync(0xffffffffu, la, sx0);
            const float a1 = __shfl_sync(0xffffffffu, la, sx1);
            const float b0 = __shfl_sync(0xffffffffu, lb, sx0);
            const float b1 = __shfl_sync(0xffffffffu, lb, sx1);

            const float s0 = (lane < 16) ? a0 : b0;
            const float s1 = (lane < 16) ? a1 : b1;
            const float v  = fmaf(wx, s1 - s0, s0);

            if (stok) op[cc * BINS + soff] = v;
        }
    }
}

extern "C" void kernel_launch(void* const* d_in, const int* in_sizes, int n_in,
                              void* d_out, int out_size)
{
    const float* feat = (const float*)d_in[0];
    const float* rois = (const float*)d_in[1];
    float* out = (float*)d_out;

    dim3 grid(NUM_ROIS * CHUNKS_PER_ROI);   // 16384, chunk-major
    dim3 block(224);
    roi_align_kernel<<<grid, block>>>(feat, rois, out);
}